// round 1
// baseline (speedup 1.0000x reference)
#include <cuda_runtime.h>
#include <cuda_bf16.h>
#include <cstdint>
#include <cstddef>

#define BB 3
#define DD 2048
#define HH 16
#define HDIM 128
#define KVH 2
#define FF 6144
#define VV 32000
#define TT 4096
#define TPAST 4095
#define NL 4
#define GQ (HH / KVH)   // 8

// ---------------- scratch (single device symbol, no allocations) ----------------
// layout (floats):
//  g_h    @ 0        (BB*DD = 6144)
//  g_hn   @ 6144     (6144)
//  g_qkv  @ 12288    (BB*2560 = 7680)
//  g_q    @ 19968    (BB*HH*HDIM = 6144)
//  g_attn @ 26112    (6144)
//  g_gu   @ 32256    (BB*2*FF = 36864)
//  g_part @ 69120    (1048576)
__device__ float g_scratch[69120 + 1048576];

// ---------------- rmsnorm: y[b,:] = x[b,:] * rsqrt(mean(x^2)+eps) * w ----------------
__global__ void k_rmsnorm(const float* __restrict__ x, const float* __restrict__ w,
                          float* __restrict__ y) {
    int b = blockIdx.x;
    const float* xb = x + b * DD;
    __shared__ float red[256];
    float ss = 0.f;
    for (int i = threadIdx.x; i < DD; i += 256) { float v = xb[i]; ss += v * v; }
    red[threadIdx.x] = ss;
    __syncthreads();
    for (int s = 128; s > 0; s >>= 1) {
        if (threadIdx.x < s) red[threadIdx.x] += red[threadIdx.x + s];
        __syncthreads();
    }
    float rs = rsqrtf(red[0] * (1.f / DD) + 1e-6f);
    for (int i = threadIdx.x; i < DD; i += 256) y[b * DD + i] = xb[i] * rs * w[i];
}

// ---------------- split-K GEMV partial ----------------
// x (or silu(g)*u) is [BB, xstride]; block (bx,by): columns, D-chunk by.
// Up to 3 column segments with independent weight matrices [D, n_i] row-major.
// partial[by][b][n] written.
__global__ void k_gemv(const float* __restrict__ x,
                       const float* __restrict__ xg, const float* __restrict__ xu,
                       int xstride,
                       const float* __restrict__ W0, int n0,
                       const float* __restrict__ W1, int n1,
                       const float* __restrict__ W2, int n2,
                       int Ntot, int Dc, float* __restrict__ part) {
    extern __shared__ float xs[];   // BB * Dc
    int d0 = blockIdx.y * Dc;
    for (int i = threadIdx.x; i < BB * Dc; i += blockDim.x) {
        int b = i / Dc, d = i - b * Dc;
        float v;
        if (xg) {
            float g = xg[b * xstride + d0 + d];
            float u = xu[b * xstride + d0 + d];
            v = (g / (1.f + __expf(-g))) * u;   // silu(g)*u
        } else {
            v = x[b * xstride + d0 + d];
        }
        xs[i] = v;
    }
    __syncthreads();

    int n = (blockIdx.x * blockDim.x + threadIdx.x) * 4;
    if (n >= Ntot) return;
    const float* Wp; int c, ld;
    if (n < n0)            { Wp = W0; c = n;           ld = n0; }
    else if (n < n0 + n1)  { Wp = W1; c = n - n0;      ld = n1; }
    else                   { Wp = W2; c = n - n0 - n1; ld = n2; }

    const float4* Wr = reinterpret_cast<const float4*>(Wp + (size_t)d0 * ld + c);
    size_t ld4 = (size_t)(ld >> 2);
    float4 a0 = {0,0,0,0}, a1 = {0,0,0,0}, a2 = {0,0,0,0};
#pragma unroll 4
    for (int d = 0; d < Dc; ++d) {
        float4 w = __ldg(Wr + (size_t)d * ld4);
        float x0 = xs[d], x1 = xs[Dc + d], x2 = xs[2 * Dc + d];
        a0.x += x0 * w.x; a0.y += x0 * w.y; a0.z += x0 * w.z; a0.w += x0 * w.w;
        a1.x += x1 * w.x; a1.y += x1 * w.y; a1.z += x1 * w.z; a1.w += x1 * w.w;
        a2.x += x2 * w.x; a2.y += x2 * w.y; a2.z += x2 * w.z; a2.w += x2 * w.w;
    }
    float* P = part + (size_t)blockIdx.y * BB * Ntot;
    *(float4*)(P + 0 * (size_t)Ntot + n) = a0;
    *(float4*)(P + 1 * (size_t)Ntot + n) = a1;
    *(float4*)(P + 2 * (size_t)Ntot + n) = a2;
}

// ---------------- reduce over splits + optional residual adds ----------------
__global__ void k_reduce(const float* __restrict__ part, int S, int Ntot,
                         const float* __restrict__ r1, const float* __restrict__ r2,
                         float* __restrict__ y) {
    int tot = BB * Ntot;
    for (int i = blockIdx.x * 256 + threadIdx.x; i < tot; i += gridDim.x * 256) {
        float a = r1 ? r1[i] : 0.f;
        if (r2) a += r2[i];
        for (int s = 0; s < S; ++s) a += part[(size_t)s * tot + i];
        y[i] = a;
    }
}

// ---------------- per-head RMSNorm (+scale) + RoPE; write q scratch & new k/v ----------------
__global__ void k_rope(const float* __restrict__ qkv,
                       const float* __restrict__ wqn, const float* __restrict__ wkn,
                       const float* __restrict__ cq, const float* __restrict__ sq,
                       const float* __restrict__ ck, const float* __restrict__ sk,
                       float* __restrict__ qout, float* __restrict__ kcache,
                       float* __restrict__ vcache, int l) {
    __shared__ float nsh[HDIM];
    __shared__ float red[4];
    int t = threadIdx.x;                // 0..127
    int blk = blockIdx.x;
    const float scale = 0.29730177875068026f;  // 128^-0.25
    if (blk < BB * HH) {
        int b = blk / HH, h = blk % HH;
        float v = qkv[b * 2560 + h * HDIM + t];
        float ss = v * v;
        for (int o = 16; o; o >>= 1) ss += __shfl_xor_sync(0xffffffff, ss, o);
        if ((t & 31) == 0) red[t >> 5] = ss;
        __syncthreads();
        float tot = red[0] + red[1] + red[2] + red[3];
        float rs = rsqrtf(tot * (1.f / HDIM) + 1e-6f);
        float nv = v * rs * wqn[t] * scale;
        nsh[t] = nv;
        __syncthreads();
        float partner = (t < 64) ? -nsh[t + 64] : nsh[t - 64];
        qout[b * HH * HDIM + h * HDIM + t] = nv * cq[t] + partner * sq[t];
    } else {
        int j = blk - BB * HH;
        int b = j / KVH, kh = j % KVH;
        float v = qkv[b * 2560 + 2048 + kh * HDIM + t];
        float ss = v * v;
        for (int o = 16; o; o >>= 1) ss += __shfl_xor_sync(0xffffffff, ss, o);
        if ((t & 31) == 0) red[t >> 5] = ss;
        __syncthreads();
        float tot = red[0] + red[1] + red[2] + red[3];
        float rs = rsqrtf(tot * (1.f / HDIM) + 1e-6f);
        float nv = v * rs * wkn[t] * scale;
        nsh[t] = nv;
        __syncthreads();
        float partner = (t < 64) ? -nsh[t + 64] : nsh[t - 64];
        float kval = nv * ck[t] + partner * sk[t];
        size_t kb = ((size_t)(l * BB + b) * KVH + kh) * (size_t)HDIM * TT;
        kcache[kb + (size_t)t * TT + TPAST] = kval;
        size_t vb = ((size_t)(l * BB + b) * KVH + kh) * (size_t)TT * HDIM;
        vcache[vb + (size_t)TPAST * HDIM + t] = qkv[b * 2560 + 2304 + kh * HDIM + t];
    }
}

// ---------------- GQA decode attention: one block per (b,h) ----------------
__global__ void k_attn(const float* __restrict__ q, const float* __restrict__ kc,
                       const float* __restrict__ vc, const float* __restrict__ ascale_p,
                       float* __restrict__ out, int l) {
    __shared__ float sc[TT];          // scores -> probs
    __shared__ float qs[HDIM];
    __shared__ float red[256];
    __shared__ float4 red4[8][32];
    int tid = threadIdx.x;
    int b = blockIdx.x / HH, h = blockIdx.x % HH;
    int kh = h >> 3;
    if (tid < HDIM) qs[tid] = q[b * HH * HDIM + h * HDIM + tid];
    __syncthreads();

    // phase 1: scores[t] = q . K[:,t]
    const float4* K4 = (const float4*)(kc + (((size_t)(l * BB + b) * KVH + kh) * HDIM) * TT);
    float4 acc[4] = {};
#pragma unroll 2
    for (int d = 0; d < HDIM; ++d) {
        float qv = qs[d];
        const float4* Kr = K4 + (size_t)d * (TT / 4);
#pragma unroll
        for (int g = 0; g < 4; ++g) {
            float4 kv = __ldg(Kr + g * 256 + tid);
            acc[g].x += qv * kv.x; acc[g].y += qv * kv.y;
            acc[g].z += qv * kv.z; acc[g].w += qv * kv.w;
        }
    }
    float madd = -128.f * ascale_p[0];   // mask for t>0 (zero in decode)
    float lmax = -1e30f;
#pragma unroll
    for (int g = 0; g < 4; ++g) {
        int tb = (g * 256 + tid) * 4;
        float4 a = acc[g];
        a.x += (tb == 0) ? 0.f : madd;
        a.y += madd; a.z += madd; a.w += madd;
        sc[tb] = a.x; sc[tb + 1] = a.y; sc[tb + 2] = a.z; sc[tb + 3] = a.w;
        lmax = fmaxf(lmax, fmaxf(fmaxf(a.x, a.y), fmaxf(a.z, a.w)));
    }
    red[tid] = lmax;
    __syncthreads();
    for (int s = 128; s > 0; s >>= 1) {
        if (tid < s) red[tid] = fmaxf(red[tid], red[tid + s]);
        __syncthreads();
    }
    float m = red[0];
    __syncthreads();

    float lsum = 0.f;
#pragma unroll
    for (int g = 0; g < 4; ++g) {
        int tb = (g * 256 + tid) * 4;
#pragma unroll
        for (int c = 0; c < 4; ++c) {
            float e = __expf(sc[tb + c] - m);
            sc[tb + c] = e;
            lsum += e;
        }
    }
    red[tid] = lsum;
    __syncthreads();
    for (int s = 128; s > 0; s >>= 1) {
        if (tid < s) red[tid] += red[tid + s];
        __syncthreads();
    }
    float inv = 1.f / red[0];
    __syncthreads();

    // phase 2: out[d] = sum_t p[t] * V[t,d]
    int d4 = tid & 31, tq = tid >> 5;
    const float4* V4 = (const float4*)(vc + ((size_t)(l * BB + b) * KVH + kh) * (size_t)TT * HDIM);
    float4 o = {0, 0, 0, 0};
    int t0 = tq * 512;
#pragma unroll 4
    for (int t = t0; t < t0 + 512; ++t) {
        float p = sc[t];
        float4 v = __ldg(V4 + (size_t)t * 32 + d4);
        o.x += p * v.x; o.y += p * v.y; o.z += p * v.z; o.w += p * v.w;
    }
    red4[tq][d4] = o;
    __syncthreads();
    if (tid < 32) {
        float4 s = red4[0][tid];
#pragma unroll
        for (int g = 1; g < 8; ++g) {
            float4 r = red4[g][tid];
            s.x += r.x; s.y += r.y; s.z += r.z; s.w += r.w;
        }
        s.x *= inv; s.y *= inv; s.z *= inv; s.w *= inv;
        *(float4*)(out + b * HH * HDIM + h * HDIM + tid * 4) = s;
    }
}

// ---------------- past-cache copies into output KV regions ----------------
__global__ void k_copy_k(const float* __restrict__ pk, float* __restrict__ outk) {
    const int total = NL * BB * KVH * HDIM * TPAST;   // 12,579,840
    for (int i = blockIdx.x * blockDim.x + threadIdx.x; i < total;
         i += gridDim.x * blockDim.x) {
        int row = i / TPAST;
        int t = i - row * TPAST;
        outk[(size_t)row * TT + t] = pk[i];
    }
}
__global__ void k_copy_v(const float4* __restrict__ pv, float4* __restrict__ outv) {
    const int total4 = NL * BB * KVH * TPAST * HDIM / 4;  // 3,144,960
    const int per = TPAST * HDIM / 4;                     // 131,040
    for (int i = blockIdx.x * blockDim.x + threadIdx.x; i < total4;
         i += gridDim.x * blockDim.x) {
        int lbk = i / per;
        int rem = i - lbk * per;
        outv[(size_t)lbk * (TT * HDIM / 4) + rem] = pv[i];
    }
}

// ---------------- host ----------------
extern "C" void kernel_launch(void* const* d_in, const int* in_sizes, int n_in,
                              void* d_out, int out_size) {
    const float* hid   = (const float*)d_in[0];
    const float* pastk = (const float*)d_in[1];
    const float* pastv = (const float*)d_in[2];
    const float* deeps = (const float*)d_in[3];
    const float* cosq  = (const float*)d_in[4];
    const float* sinq  = (const float*)d_in[5];
    const float* cosk  = (const float*)d_in[6];
    const float* sink  = (const float*)d_in[7];
    const float* ascl  = (const float*)d_in[8];
    const float* w_in  = (const float*)d_in[9];
    const float* wq    = (const float*)d_in[10];
    const float* wk    = (const float*)d_in[11];
    const float* wv    = (const float*)d_in[12];
    const float* wqn   = (const float*)d_in[13];
    const float* wkn   = (const float*)d_in[14];
    const float* wo    = (const float*)d_in[15];
    const float* wpost = (const float*)d_in[16];
    const float* wgate = (const float*)d_in[17];
    const float* wup   = (const float*)d_in[18];
    const float* wdown = (const float*)d_in[19];
    const float* wfin  = (const float*)d_in[20];
    const float* wlm   = (const float*)d_in[21];

    float* out  = (float*)d_out;
    float* outk = out + BB * VV;                               // 96000
    float* outv = outk + (size_t)NL * BB * KVH * HDIM * TT;    // +12,582,912

    static float* sp = nullptr;
    if (!sp) cudaGetSymbolAddress((void**)&sp, g_scratch);
    float* g_h    = sp;
    float* g_hn   = sp + 6144;
    float* g_qkv  = sp + 12288;
    float* g_q    = sp + 19968;
    float* g_attn = sp + 26112;
    float* g_gu   = sp + 32256;
    float* g_part = sp + 69120;

    k_copy_k<<<1024, 256>>>(pastk, outk);
    k_copy_v<<<1024, 256>>>((const float4*)pastv, (float4*)outv);

    const float* hptr = hid;
    for (int l = 0; l < NL; ++l) {
        // pre-attn norm
        k_rmsnorm<<<BB, 256>>>(hptr, w_in + l * DD, g_hn);
        // fused QKV GEMV (segments: wq|wk|wv), Ntot=2560, D=2048, S=32
        {
            dim3 grid(3, 32); int Dc = DD / 32;
            k_gemv<<<grid, 256, BB * Dc * 4>>>(g_hn, nullptr, nullptr, DD,
                wq + (size_t)l * DD * 2048, 2048,
                wk + (size_t)l * DD * 256, 256,
                wv + (size_t)l * DD * 256, 256,
                2560, Dc, g_part);
            k_reduce<<<30, 256>>>(g_part, 32, 2560, nullptr, nullptr, g_qkv);
        }
        // qk-norm + RoPE + write new k/v column
        k_rope<<<BB * HH + BB * KVH, 128>>>(g_qkv, wqn + l * HDIM, wkn + l * HDIM,
                                            cosq, sinq, cosk, sink,
                                            g_q, outk, outv, l);
        // attention
        k_attn<<<BB * HH, 256>>>(g_q, outk, outv, ascl, g_attn, l);
        // wo GEMV + residual
        {
            dim3 grid(2, 32); int Dc = DD / 32;
            k_gemv<<<grid, 256, BB * Dc * 4>>>(g_attn, nullptr, nullptr, DD,
                wo + (size_t)l * DD * DD, DD, nullptr, 0, nullptr, 0,
                DD, Dc, g_part);
            k_reduce<<<24, 256>>>(g_part, 32, DD, hptr, nullptr, g_h);
        }
        // post norm
        k_rmsnorm<<<BB, 256>>>(g_h, wpost + l * DD, g_hn);
        // gate|up GEMV, Ntot=12288, D=2048, S=16
        {
            dim3 grid(12, 16); int Dc = DD / 16;
            k_gemv<<<grid, 256, BB * Dc * 4>>>(g_hn, nullptr, nullptr, DD,
                wgate + (size_t)l * DD * FF, FF,
                wup + (size_t)l * DD * FF, FF,
                nullptr, 0, 2 * FF, Dc, g_part);
            k_reduce<<<144, 256>>>(g_part, 16, 2 * FF, nullptr, nullptr, g_gu);
        }
        // down GEMV with fused silu(g)*u, D=6144, S=48; +residual +deepstack
        {
            dim3 grid(2, 48); int Dc = FF / 48;
            k_gemv<<<grid, 256, BB * Dc * 4>>>(nullptr, g_gu, g_gu + FF, 2 * FF,
                wdown + (size_t)l * FF * DD, DD, nullptr, 0, nullptr, 0,
                DD, Dc, g_part);
            const float* ds = (l < 3) ? (deeps + (size_t)l * BB * DD) : nullptr;
            k_reduce<<<24, 256>>>(g_part, 48, DD, g_h, ds, g_h);
        }
        hptr = g_h;
    }
    // final norm + lm_head
    k_rmsnorm<<<BB, 256>>>(g_h, wfin, g_hn);
    {
        dim3 grid(32, 8); int Dc = DD / 8;
        k_gemv<<<grid, 256, BB * Dc * 4>>>(g_hn, nullptr, nullptr, DD,
            wlm, VV, nullptr, 0, nullptr, 0, VV, Dc, g_part);
        k_reduce<<<375, 256>>>(g_part, 8, VV, nullptr, nullptr, out);
    }
}

// round 3
// speedup vs baseline: 1.8132x; 1.8132x over previous
#include <cuda_runtime.h>
#include <cuda_bf16.h>
#include <cstdint>
#include <cstddef>

#define BB 3
#define DD 2048
#define HH 16
#define HDIM 128
#define KVH 2
#define FF 6144
#define VV 32000
#define TT 4096
#define TPAST 4095
#define NL 4
#define GQ (HH / KVH)   // 8
#define NCH 32          // attention chunks over T
#define CT 128          // tokens per chunk
#define CS (GQ * HDIM + 2 * GQ)   // 1040 floats per attn chunk record

// ---------------- scratch ----------------
__device__ float g_scratch[268800 + 1600000];

// ---------------- rmsnorm ----------------
__global__ void k_rmsnorm(const float* __restrict__ x, const float* __restrict__ w,
                          float* __restrict__ y) {
    int b = blockIdx.x;
    const float* xb = x + b * DD;
    __shared__ float red[256];
    float ss = 0.f;
    for (int i = threadIdx.x; i < DD; i += 256) { float v = xb[i]; ss += v * v; }
    red[threadIdx.x] = ss;
    __syncthreads();
    for (int s = 128; s > 0; s >>= 1) {
        if (threadIdx.x < s) red[threadIdx.x] += red[threadIdx.x + s];
        __syncthreads();
    }
    float rs = rsqrtf(red[0] * (1.f / DD) + 1e-6f);
    for (int i = threadIdx.x; i < DD; i += 256) y[b * DD + i] = xb[i] * rs * w[i];
}

// ---------------- split-K GEMV partial (templated D-chunk, batched loads) ----------------
template <int DC>
__global__ __launch_bounds__(256) void k_gemv_t(
        const float* __restrict__ x,
        const float* __restrict__ xg, const float* __restrict__ xu, int xstride,
        const float* __restrict__ W0, int n0,
        const float* __restrict__ W1, int n1,
        const float* __restrict__ W2, int n2,
        int Ntot, float* __restrict__ part) {
    __shared__ float xs[BB * DC];
    int d0 = blockIdx.y * DC;
    for (int i = threadIdx.x; i < BB * DC; i += 256) {
        int b = i / DC, d = i - b * DC;
        float v;
        if (xg) {
            float g = xg[b * xstride + d0 + d];
            float u = xu[b * xstride + d0 + d];
            v = (g / (1.f + __expf(-g))) * u;
        } else {
            v = x[b * xstride + d0 + d];
        }
        xs[i] = v;
    }
    __syncthreads();

    int n = (blockIdx.x * 256 + threadIdx.x) * 4;
    if (n >= Ntot) return;
    const float* Wp; int c, ld;
    if (n < n0)            { Wp = W0; c = n;           ld = n0; }
    else if (n < n0 + n1)  { Wp = W1; c = n - n0;      ld = n1; }
    else                   { Wp = W2; c = n - n0 - n1; ld = n2; }

    const float4* Wr = reinterpret_cast<const float4*>(Wp + (size_t)d0 * ld) + (c >> 2);
    size_t ld4 = (size_t)(ld >> 2);
    float4 a0 = {0,0,0,0}, a1 = {0,0,0,0}, a2 = {0,0,0,0};
    for (int d = 0; d < DC; d += 8) {
        float4 w[8];
#pragma unroll
        for (int u = 0; u < 8; ++u) w[u] = __ldg(Wr + (size_t)(d + u) * ld4);
#pragma unroll
        for (int u = 0; u < 8; ++u) {
            float x0 = xs[d + u], x1 = xs[DC + d + u], x2 = xs[2 * DC + d + u];
            a0.x += x0 * w[u].x; a0.y += x0 * w[u].y; a0.z += x0 * w[u].z; a0.w += x0 * w[u].w;
            a1.x += x1 * w[u].x; a1.y += x1 * w[u].y; a1.z += x1 * w[u].z; a1.w += x1 * w[u].w;
            a2.x += x2 * w[u].x; a2.y += x2 * w[u].y; a2.z += x2 * w[u].z; a2.w += x2 * w[u].w;
        }
    }
    float* P = part + (size_t)blockIdx.y * BB * Ntot;
    *(float4*)(P + 0 * (size_t)Ntot + n) = a0;
    *(float4*)(P + 1 * (size_t)Ntot + n) = a1;
    *(float4*)(P + 2 * (size_t)Ntot + n) = a2;
}

// ---------------- reduce over splits + optional residual adds ----------------
__global__ void k_reduce(const float* __restrict__ part, int S, int Ntot,
                         const float* __restrict__ r1, const float* __restrict__ r2,
                         float* __restrict__ y) {
    int tot = BB * Ntot;
    for (int i = blockIdx.x * 256 + threadIdx.x; i < tot; i += gridDim.x * 256) {
        float a = r1 ? r1[i] : 0.f;
        if (r2) a += r2[i];
        for (int s = 0; s < S; ++s) a += part[(size_t)s * tot + i];
        y[i] = a;
    }
}

// ---------------- per-head RMSNorm + RoPE; write q scratch & new k/v column ----------------
__global__ void k_rope(const float* __restrict__ qkv,
                       const float* __restrict__ wqn, const float* __restrict__ wkn,
                       const float* __restrict__ cq, const float* __restrict__ sq,
                       const float* __restrict__ ck, const float* __restrict__ sk,
                       float* __restrict__ qout, float* __restrict__ kcache,
                       float* __restrict__ vcache, int l) {
    __shared__ float nsh[HDIM];
    __shared__ float red[4];
    int t = threadIdx.x;
    int blk = blockIdx.x;
    const float scale = 0.29730177875068026f;  // 128^-0.25
    if (blk < BB * HH) {
        int b = blk / HH, h = blk % HH;
        float v = qkv[b * 2560 + h * HDIM + t];
        float ss = v * v;
        for (int o = 16; o; o >>= 1) ss += __shfl_xor_sync(0xffffffff, ss, o);
        if ((t & 31) == 0) red[t >> 5] = ss;
        __syncthreads();
        float tot = red[0] + red[1] + red[2] + red[3];
        float rs = rsqrtf(tot * (1.f / HDIM) + 1e-6f);
        float nv = v * rs * wqn[t] * scale;
        nsh[t] = nv;
        __syncthreads();
        float partner = (t < 64) ? -nsh[t + 64] : nsh[t - 64];
        qout[b * HH * HDIM + h * HDIM + t] = nv * cq[t] + partner * sq[t];
    } else {
        int j = blk - BB * HH;
        int b = j / KVH, kh = j % KVH;
        float v = qkv[b * 2560 + 2048 + kh * HDIM + t];
        float ss = v * v;
        for (int o = 16; o; o >>= 1) ss += __shfl_xor_sync(0xffffffff, ss, o);
        if ((t & 31) == 0) red[t >> 5] = ss;
        __syncthreads();
        float tot = red[0] + red[1] + red[2] + red[3];
        float rs = rsqrtf(tot * (1.f / HDIM) + 1e-6f);
        float nv = v * rs * wkn[t] * scale;
        nsh[t] = nv;
        __syncthreads();
        float partner = (t < 64) ? -nsh[t + 64] : nsh[t - 64];
        float kval = nv * ck[t] + partner * sk[t];
        size_t kb = ((size_t)(l * BB + b) * KVH + kh) * (size_t)HDIM * TT;
        kcache[kb + (size_t)t * TT + TPAST] = kval;
        size_t vb = ((size_t)(l * BB + b) * KVH + kh) * (size_t)TT * HDIM;
        vcache[vb + (size_t)TPAST * HDIM + t] = qkv[b * 2560 + 2304 + kh * HDIM + t];
    }
}

// ---------------- flash-decode attention: partial per (b,kh,chunk) ----------------
// dyn smem: tile[16384] | qs[1024] | ps[1024]  = 18432 floats (73728 B)
__global__ __launch_bounds__(256) void k_attn_part(
        const float* __restrict__ q, const float* __restrict__ kc,
        const float* __restrict__ vc, const float* __restrict__ ascale_p,
        float* __restrict__ po, int l) {
    extern __shared__ float smem[];
    float* tile = smem;              // 128x128, K as [d][t] then V as [t][d]
    float* qs   = smem + 16384;      // [GQ][HDIM]
    float* ps   = smem + 17408;      // [GQ][CT] scores -> probs
    int tid = threadIdx.x;
    int c = blockIdx.x;
    int by = blockIdx.y;             // b*KVH + kh
    int b = by / KVH, kh = by % KVH;
    int t0 = c * CT;
    float madd = -128.f * ascale_p[0];

    // q for this kv-head's 8 query heads (contiguous in g_q): 1024 floats
    {
        float4 v = *(const float4*)(q + b * HH * HDIM + kh * GQ * HDIM + tid * 4);
        *(float4*)(qs + tid * 4) = v;
    }
    // load K tile [d][t]
    {
        const float* Kb = kc + (((size_t)(l * BB + b) * KVH + kh) * HDIM) * TT + t0;
        const float4* Ks = (const float4*)Kb;
        float4* Td = (float4*)tile;
        for (int i = tid; i < HDIM * CT / 4; i += 256) {
            int row = i >> 5, col = i & 31;
            Td[i] = __ldg(Ks + (size_t)row * (TT / 4) + col);
        }
    }
    __syncthreads();

    // scores: 4 heads per thread
    {
        int t = tid & 127, hb = tid >> 7;
        float a[4] = {0.f, 0.f, 0.f, 0.f};
        for (int d = 0; d < HDIM; ++d) {
            float kv = tile[d * CT + t];
#pragma unroll
            for (int g2 = 0; g2 < 4; ++g2)
                a[g2] += kv * qs[(hb * 4 + g2) * HDIM + d];
        }
        float mk = (t0 + t > 0) ? madd : 0.f;
#pragma unroll
        for (int g2 = 0; g2 < 4; ++g2)
            ps[(hb * 4 + g2) * CT + t] = a[g2] + mk;
    }
    __syncthreads();

    // per-head local max & exp-sum (warp w handles head w)
    {
        int w = tid >> 5, lane = tid & 31;
        float mx = -1e30f;
        for (int j = lane; j < CT; j += 32) mx = fmaxf(mx, ps[w * CT + j]);
        for (int o = 16; o; o >>= 1) mx = fmaxf(mx, __shfl_xor_sync(0xffffffff, mx, o));
        float sum = 0.f;
        for (int j = lane; j < CT; j += 32) {
            float e = __expf(ps[w * CT + j] - mx);
            ps[w * CT + j] = e;
            sum += e;
        }
        for (int o = 16; o; o >>= 1) sum += __shfl_xor_sync(0xffffffff, sum, o);
        if (lane == 0) {
            float* rec = po + ((size_t)by * NCH + c) * CS;
            rec[GQ * HDIM + w] = mx;
            rec[GQ * HDIM + GQ + w] = sum;
        }
    }
    __syncthreads();

    // load V tile [t][d]
    {
        const float4* Vs = (const float4*)(vc +
            ((size_t)(l * BB + b) * KVH + kh) * (size_t)TT * HDIM + (size_t)t0 * HDIM);
        float4* Td = (float4*)tile;
        for (int i = tid; i < CT * HDIM / 4; i += 256) Td[i] = __ldg(Vs + i);
    }
    __syncthreads();

    // o[h][d] partial
    {
        int d = tid & 127, hb = tid >> 7;
        float o[4] = {0.f, 0.f, 0.f, 0.f};
        for (int t = 0; t < CT; ++t) {
            float vv = tile[t * HDIM + d];
#pragma unroll
            for (int g2 = 0; g2 < 4; ++g2)
                o[g2] += vv * ps[(hb * 4 + g2) * CT + t];
        }
        float* rec = po + ((size_t)by * NCH + c) * CS;
#pragma unroll
        for (int g2 = 0; g2 < 4; ++g2)
            rec[(hb * 4 + g2) * HDIM + d] = o[g2];
    }
}

// ---------------- combine attention chunks ----------------
__global__ void k_attn_fin(const float* __restrict__ po, float* __restrict__ out) {
    int b = blockIdx.x / HH, h = blockIdx.x % HH;
    int kh = h >> 3, g = h & 7;
    int tid = threadIdx.x;   // 128
    const float* base = po + (size_t)(b * KVH + kh) * NCH * CS;
    float m = -1e30f;
    for (int c = 0; c < NCH; ++c) m = fmaxf(m, base[c * CS + GQ * HDIM + g]);
    float den = 0.f, acc = 0.f;
    for (int c = 0; c < NCH; ++c) {
        float mc = base[c * CS + GQ * HDIM + g];
        float lc = base[c * CS + GQ * HDIM + GQ + g];
        float w = __expf(mc - m);
        den += lc * w;
        acc += base[c * CS + g * HDIM + tid] * w;
    }
    out[b * HH * HDIM + h * HDIM + tid] = acc / den;
}

// ---------------- past-cache copies ----------------
__global__ void k_copy_k(const float* __restrict__ pk, float* __restrict__ outk) {
    int r = blockIdx.x;   // NL*BB*KVH*HDIM rows
    const float* src = pk + (size_t)r * TPAST;
    float* dst = outk + (size_t)r * TT;
    for (int t = threadIdx.x; t < TPAST; t += 256) dst[t] = __ldg(src + t);
}
__global__ void k_copy_v(const float4* __restrict__ pv, float4* __restrict__ outv) {
    const int per = TPAST * HDIM / 4;   // 131040 float4 per (l,b,kh)
    int ch = blockIdx.y;
    int i = blockIdx.x * 256 + threadIdx.x;
    if (i < per)
        outv[(size_t)ch * (TT * HDIM / 4) + i] = __ldg(pv + (size_t)ch * per + i);
}

// ---------------- host ----------------
extern "C" void kernel_launch(void* const* d_in, const int* in_sizes, int n_in,
                              void* d_out, int out_size) {
    const float* hid   = (const float*)d_in[0];
    const float* pastk = (const float*)d_in[1];
    const float* pastv = (const float*)d_in[2];
    const float* deeps = (const float*)d_in[3];
    const float* cosq  = (const float*)d_in[4];
    const float* sinq  = (const float*)d_in[5];
    const float* cosk  = (const float*)d_in[6];
    const float* sink  = (const float*)d_in[7];
    const float* ascl  = (const float*)d_in[8];
    const float* w_in  = (const float*)d_in[9];
    const float* wq    = (const float*)d_in[10];
    const float* wk    = (const float*)d_in[11];
    const float* wv    = (const float*)d_in[12];
    const float* wqn   = (const float*)d_in[13];
    const float* wkn   = (const float*)d_in[14];
    const float* wo    = (const float*)d_in[15];
    const float* wpost = (const float*)d_in[16];
    const float* wgate = (const float*)d_in[17];
    const float* wup   = (const float*)d_in[18];
    const float* wdown = (const float*)d_in[19];
    const float* wfin  = (const float*)d_in[20];
    const float* wlm   = (const float*)d_in[21];

    float* out  = (float*)d_out;
    float* outk = out + BB * VV;
    float* outv = outk + (size_t)NL * BB * KVH * HDIM * TT;

    static float* sp = nullptr;
    if (!sp) {
        cudaGetSymbolAddress((void**)&sp, g_scratch);
        cudaFuncSetAttribute(k_attn_part, cudaFuncAttributeMaxDynamicSharedMemorySize,
                             73728);
    }
    float* g_h     = sp;
    float* g_hn    = sp + 6144;
    float* g_qkv   = sp + 12288;
    float* g_q     = sp + 19968;
    float* g_attn  = sp + 26112;
    float* g_gu    = sp + 32256;
    float* g_apart = sp + 69120;
    float* g_part  = sp + 268800;

    k_copy_k<<<NL * BB * KVH * HDIM, 256>>>(pastk, outk);
    {
        dim3 g((TPAST * HDIM / 4 + 255) / 256, NL * BB * KVH);
        k_copy_v<<<g, 256>>>((const float4*)pastv, (float4*)outv);
    }

    const float* hptr = hid;
    for (int l = 0; l < NL; ++l) {
        k_rmsnorm<<<BB, 256>>>(hptr, w_in + l * DD, g_hn);
        // QKV: Ntot=2560, 128 splits of 16
        k_gemv_t<16><<<dim3(3, 128), 256>>>(g_hn, nullptr, nullptr, DD,
            wq + (size_t)l * DD * 2048, 2048,
            wk + (size_t)l * DD * 256, 256,
            wv + (size_t)l * DD * 256, 256, 2560, g_part);
        k_reduce<<<30, 256>>>(g_part, 128, 2560, nullptr, nullptr, g_qkv);

        k_rope<<<BB * HH + BB * KVH, 128>>>(g_qkv, wqn + l * HDIM, wkn + l * HDIM,
                                            cosq, sinq, cosk, sink,
                                            g_q, outk, outv, l);

        k_attn_part<<<dim3(NCH, BB * KVH), 256, 73728>>>(g_q, outk, outv, ascl,
                                                         g_apart, l);
        k_attn_fin<<<BB * HH, 128>>>(g_apart, g_attn);

        // wo: N=2048, 128 splits of 16
        k_gemv_t<16><<<dim3(2, 128), 256>>>(g_attn, nullptr, nullptr, DD,
            wo + (size_t)l * DD * DD, DD, nullptr, 0, nullptr, 0, DD, g_part);
        k_reduce<<<24, 256>>>(g_part, 128, DD, hptr, nullptr, g_h);

        k_rmsnorm<<<BB, 256>>>(g_h, wpost + l * DD, g_hn);
        // gate|up: Ntot=12288, 32 splits of 64
        k_gemv_t<64><<<dim3(12, 32), 256>>>(g_hn, nullptr, nullptr, DD,
            wgate + (size_t)l * DD * FF, FF,
            wup + (size_t)l * DD * FF, FF,
            nullptr, 0, 2 * FF, g_part);
        k_reduce<<<144, 256>>>(g_part, 32, 2 * FF, nullptr, nullptr, g_gu);

        // down (fused silu*up): N=2048, 96 splits of 64 over D=6144
        k_gemv_t<64><<<dim3(2, 96), 256>>>(nullptr, g_gu, g_gu + FF, 2 * FF,
            wdown + (size_t)l * FF * DD, DD, nullptr, 0, nullptr, 0, DD, g_part);
        const float* ds = (l < 3) ? (deeps + (size_t)l * BB * DD) : nullptr;
        k_reduce<<<24, 256>>>(g_part, 96, DD, g_h, ds, g_h);
        hptr = g_h;
    }

    k_rmsnorm<<<BB, 256>>>(g_h, wfin, g_hn);
    // lm_head: N=32000, 16 splits of 128
    k_gemv_t<128><<<dim3(32, 16), 256>>>(g_hn, nullptr, nullptr, DD,
        wlm, VV, nullptr, 0, nullptr, 0, VV, g_part);
    k_reduce<<<375, 256>>>(g_part, 16, VV, nullptr, nullptr, out);
}

// round 4
// speedup vs baseline: 2.1150x; 1.1664x over previous
#include <cuda_runtime.h>
#include <cuda_bf16.h>
#include <cstdint>
#include <cstddef>

#define BB 3
#define DD 2048
#define HH 16
#define HDIM 128
#define KVH 2
#define FF 6144
#define VV 32000
#define TT 4096
#define TPAST 4095
#define NL 4
#define GQ (HH / KVH)   // 8
#define NCH 32
#define CT 128
#define CS (GQ * HDIM + 2 * GQ)   // 1040

__device__ float g_scratch[268800 + 1600000];

// ---------------- rmsnorm ----------------
__global__ void k_rmsnorm(const float* __restrict__ x, const float* __restrict__ w,
                          float* __restrict__ y) {
    int b = blockIdx.x;
    const float* xb = x + b * DD;
    __shared__ float red[256];
    float ss = 0.f;
    for (int i = threadIdx.x; i < DD; i += 256) { float v = xb[i]; ss += v * v; }
    red[threadIdx.x] = ss;
    __syncthreads();
    for (int s = 128; s > 0; s >>= 1) {
        if (threadIdx.x < s) red[threadIdx.x] += red[threadIdx.x + s];
        __syncthreads();
    }
    float rs = rsqrtf(red[0] * (1.f / DD) + 1e-6f);
    for (int i = threadIdx.x; i < DD; i += 256) y[b * DD + i] = xb[i] * rs * w[i];
}

// ---------------- split-K GEMV, software-pipelined ----------------
template <int DC>
__global__ __launch_bounds__(256) void k_gemv_t(
        const float* __restrict__ x,
        const float* __restrict__ xg, const float* __restrict__ xu, int xstride,
        const float* __restrict__ W0, int n0,
        const float* __restrict__ W1, int n1,
        const float* __restrict__ W2, int n2,
        int Ntot, float* __restrict__ part) {
    __shared__ float xs[BB * DC];
    int d0 = blockIdx.y * DC;
    int n = (blockIdx.x * 256 + threadIdx.x) * 4;
    bool active = n < Ntot;

    const float4* Wr = nullptr;
    size_t ld4 = 0;
    if (active) {
        const float* Wp; int c, ld;
        if (n < n0)            { Wp = W0; c = n;           ld = n0; }
        else if (n < n0 + n1)  { Wp = W1; c = n - n0;      ld = n1; }
        else                   { Wp = W2; c = n - n0 - n1; ld = n2; }
        Wr = reinterpret_cast<const float4*>(Wp + (size_t)d0 * ld) + (c >> 2);
        ld4 = (size_t)(ld >> 2);
    }

    // issue first weight batch BEFORE x staging (hides x-load latency)
    float4 w[8];
    if (active) {
#pragma unroll
        for (int u = 0; u < 8; ++u) w[u] = __ldg(Wr + (size_t)u * ld4);
    }

    for (int i = threadIdx.x; i < BB * DC; i += 256) {
        int b = i / DC, d = i - b * DC;
        float v;
        if (xg) {
            float g = xg[b * xstride + d0 + d];
            float u = xu[b * xstride + d0 + d];
            v = (g / (1.f + __expf(-g))) * u;
        } else {
            v = x[b * xstride + d0 + d];
        }
        xs[i] = v;
    }
    __syncthreads();

    float4 a0 = {0,0,0,0}, a1 = {0,0,0,0}, a2 = {0,0,0,0};
    if (active) {
#pragma unroll
        for (int d = 0; d < DC; d += 8) {
            float4 w2[8];
            if (d + 8 < DC) {
#pragma unroll
                for (int u = 0; u < 8; ++u)
                    w2[u] = __ldg(Wr + (size_t)(d + 8 + u) * ld4);
            }
#pragma unroll
            for (int u = 0; u < 8; ++u) {
                float x0 = xs[d + u], x1 = xs[DC + d + u], x2 = xs[2 * DC + d + u];
                a0.x += x0 * w[u].x; a0.y += x0 * w[u].y; a0.z += x0 * w[u].z; a0.w += x0 * w[u].w;
                a1.x += x1 * w[u].x; a1.y += x1 * w[u].y; a1.z += x1 * w[u].z; a1.w += x1 * w[u].w;
                a2.x += x2 * w[u].x; a2.y += x2 * w[u].y; a2.z += x2 * w[u].z; a2.w += x2 * w[u].w;
            }
            if (d + 8 < DC) {
#pragma unroll
                for (int u = 0; u < 8; ++u) w[u] = w2[u];
            }
        }
        float* P = part + (size_t)blockIdx.y * BB * Ntot;
        *(float4*)(P + 0 * (size_t)Ntot + n) = a0;
        *(float4*)(P + 1 * (size_t)Ntot + n) = a1;
        *(float4*)(P + 2 * (size_t)Ntot + n) = a2;
    }
}

// ---------------- reduce over splits (+residuals), float4 ----------------
__global__ void k_reduce(const float* __restrict__ part, int S, int Ntot,
                         const float* __restrict__ r1, const float* __restrict__ r2,
                         float* __restrict__ y) {
    int tot4 = BB * Ntot / 4;
    const float4* P4 = (const float4*)part;
    for (int i = blockIdx.x * 256 + threadIdx.x; i < tot4; i += gridDim.x * 256) {
        float4 a = {0,0,0,0};
        if (r1) a = ((const float4*)r1)[i];
        if (r2) { float4 t = ((const float4*)r2)[i]; a.x += t.x; a.y += t.y; a.z += t.z; a.w += t.w; }
        for (int s = 0; s < S; ++s) {
            float4 p = P4[(size_t)s * tot4 + i];
            a.x += p.x; a.y += p.y; a.z += p.z; a.w += p.w;
        }
        ((float4*)y)[i] = a;
    }
}

// ---------------- per-head RMSNorm + RoPE ----------------
__global__ void k_rope(const float* __restrict__ qkv,
                       const float* __restrict__ wqn, const float* __restrict__ wkn,
                       const float* __restrict__ cq, const float* __restrict__ sq,
                       const float* __restrict__ ck, const float* __restrict__ sk,
                       float* __restrict__ qout, float* __restrict__ kcache,
                       float* __restrict__ vcache, int l) {
    __shared__ float nsh[HDIM];
    __shared__ float red[4];
    int t = threadIdx.x;
    int blk = blockIdx.x;
    const float scale = 0.29730177875068026f;  // 128^-0.25
    if (blk < BB * HH) {
        int b = blk / HH, h = blk % HH;
        float v = qkv[b * 2560 + h * HDIM + t];
        float ss = v * v;
        for (int o = 16; o; o >>= 1) ss += __shfl_xor_sync(0xffffffff, ss, o);
        if ((t & 31) == 0) red[t >> 5] = ss;
        __syncthreads();
        float tot = red[0] + red[1] + red[2] + red[3];
        float rs = rsqrtf(tot * (1.f / HDIM) + 1e-6f);
        float nv = v * rs * wqn[t] * scale;
        nsh[t] = nv;
        __syncthreads();
        float partner = (t < 64) ? -nsh[t + 64] : nsh[t - 64];
        qout[b * HH * HDIM + h * HDIM + t] = nv * cq[t] + partner * sq[t];
    } else {
        int j = blk - BB * HH;
        int b = j / KVH, kh = j % KVH;
        float v = qkv[b * 2560 + 2048 + kh * HDIM + t];
        float ss = v * v;
        for (int o = 16; o; o >>= 1) ss += __shfl_xor_sync(0xffffffff, ss, o);
        if ((t & 31) == 0) red[t >> 5] = ss;
        __syncthreads();
        float tot = red[0] + red[1] + red[2] + red[3];
        float rs = rsqrtf(tot * (1.f / HDIM) + 1e-6f);
        float nv = v * rs * wkn[t] * scale;
        nsh[t] = nv;
        __syncthreads();
        float partner = (t < 64) ? -nsh[t + 64] : nsh[t - 64];
        float kval = nv * ck[t] + partner * sk[t];
        size_t kb = ((size_t)(l * BB + b) * KVH + kh) * (size_t)HDIM * TT;
        kcache[kb + (size_t)t * TT + TPAST] = kval;
        size_t vb = ((size_t)(l * BB + b) * KVH + kh) * (size_t)TT * HDIM;
        vcache[vb + (size_t)TPAST * HDIM + t] = qkv[b * 2560 + 2304 + kh * HDIM + t];
    }
}

// ---------------- flash-decode attention partial ----------------
__global__ __launch_bounds__(256) void k_attn_part(
        const float* __restrict__ q, const float* __restrict__ kc,
        const float* __restrict__ vc, const float* __restrict__ ascale_p,
        float* __restrict__ po, int l) {
    extern __shared__ float smem[];
    float* tile = smem;
    float* qs   = smem + 16384;
    float* ps   = smem + 17408;
    int tid = threadIdx.x;
    int c = blockIdx.x;
    int by = blockIdx.y;
    int b = by / KVH, kh = by % KVH;
    int t0 = c * CT;
    float madd = -128.f * ascale_p[0];

    {
        float4 v = *(const float4*)(q + b * HH * HDIM + kh * GQ * HDIM + tid * 4);
        *(float4*)(qs + tid * 4) = v;
    }
    {
        const float* Kb = kc + (((size_t)(l * BB + b) * KVH + kh) * HDIM) * TT + t0;
        const float4* Ks = (const float4*)Kb;
        float4* Td = (float4*)tile;
        for (int i = tid; i < HDIM * CT / 4; i += 256) {
            int row = i >> 5, col = i & 31;
            Td[i] = __ldg(Ks + (size_t)row * (TT / 4) + col);
        }
    }
    __syncthreads();

    {
        int t = tid & 127, hb = tid >> 7;
        float a[4] = {0.f, 0.f, 0.f, 0.f};
        for (int d = 0; d < HDIM; ++d) {
            float kv = tile[d * CT + t];
#pragma unroll
            for (int g2 = 0; g2 < 4; ++g2)
                a[g2] += kv * qs[(hb * 4 + g2) * HDIM + d];
        }
        float mk = (t0 + t > 0) ? madd : 0.f;
#pragma unroll
        for (int g2 = 0; g2 < 4; ++g2)
            ps[(hb * 4 + g2) * CT + t] = a[g2] + mk;
    }
    __syncthreads();

    {
        int w = tid >> 5, lane = tid & 31;
        float mx = -1e30f;
        for (int j = lane; j < CT; j += 32) mx = fmaxf(mx, ps[w * CT + j]);
        for (int o = 16; o; o >>= 1) mx = fmaxf(mx, __shfl_xor_sync(0xffffffff, mx, o));
        float sum = 0.f;
        for (int j = lane; j < CT; j += 32) {
            float e = __expf(ps[w * CT + j] - mx);
            ps[w * CT + j] = e;
            sum += e;
        }
        for (int o = 16; o; o >>= 1) sum += __shfl_xor_sync(0xffffffff, sum, o);
        if (lane == 0) {
            float* rec = po + ((size_t)by * NCH + c) * CS;
            rec[GQ * HDIM + w] = mx;
            rec[GQ * HDIM + GQ + w] = sum;
        }
    }
    __syncthreads();

    {
        const float4* Vs = (const float4*)(vc +
            ((size_t)(l * BB + b) * KVH + kh) * (size_t)TT * HDIM + (size_t)t0 * HDIM);
        float4* Td = (float4*)tile;
        for (int i = tid; i < CT * HDIM / 4; i += 256) Td[i] = __ldg(Vs + i);
    }
    __syncthreads();

    {
        int d = tid & 127, hb = tid >> 7;
        float o[4] = {0.f, 0.f, 0.f, 0.f};
        for (int t = 0; t < CT; ++t) {
            float vv = tile[t * HDIM + d];
#pragma unroll
            for (int g2 = 0; g2 < 4; ++g2)
                o[g2] += vv * ps[(hb * 4 + g2) * CT + t];
        }
        float* rec = po + ((size_t)by * NCH + c) * CS;
#pragma unroll
        for (int g2 = 0; g2 < 4; ++g2)
            rec[(hb * 4 + g2) * HDIM + d] = o[g2];
    }
}

// ---------------- combine attention chunks ----------------
__global__ void k_attn_fin(const float* __restrict__ po, float* __restrict__ out) {
    int b = blockIdx.x / HH, h = blockIdx.x % HH;
    int kh = h >> 3, g = h & 7;
    int tid = threadIdx.x;
    const float* base = po + (size_t)(b * KVH + kh) * NCH * CS;
    float m = -1e30f;
    for (int c = 0; c < NCH; ++c) m = fmaxf(m, base[c * CS + GQ * HDIM + g]);
    float den = 0.f, acc = 0.f;
    for (int c = 0; c < NCH; ++c) {
        float mc = base[c * CS + GQ * HDIM + g];
        float lc = base[c * CS + GQ * HDIM + GQ + g];
        float w = __expf(mc - m);
        den += lc * w;
        acc += base[c * CS + g * HDIM + tid] * w;
    }
    out[b * HH * HDIM + h * HDIM + tid] = acc / den;
}

// ---------------- past-cache copies ----------------
__global__ void k_copy_k(const float* __restrict__ pk, float* __restrict__ outk) {
    int r = blockIdx.x;
    const float* src = pk + (size_t)r * TPAST;
    float* dst = outk + (size_t)r * TT;
    for (int t = threadIdx.x; t < TPAST; t += 256) dst[t] = __ldg(src + t);
}
__global__ void k_copy_v(const float4* __restrict__ pv, float4* __restrict__ outv) {
    const int per = TPAST * HDIM / 4;
    int ch = blockIdx.y;
    int i = blockIdx.x * 256 + threadIdx.x;
    if (i < per)
        outv[(size_t)ch * (TT * HDIM / 4) + i] = __ldg(pv + (size_t)ch * per + i);
}

// ---------------- host ----------------
extern "C" void kernel_launch(void* const* d_in, const int* in_sizes, int n_in,
                              void* d_out, int out_size) {
    const float* hid   = (const float*)d_in[0];
    const float* pastk = (const float*)d_in[1];
    const float* pastv = (const float*)d_in[2];
    const float* deeps = (const float*)d_in[3];
    const float* cosq  = (const float*)d_in[4];
    const float* sinq  = (const float*)d_in[5];
    const float* cosk  = (const float*)d_in[6];
    const float* sink  = (const float*)d_in[7];
    const float* ascl  = (const float*)d_in[8];
    const float* w_in  = (const float*)d_in[9];
    const float* wq    = (const float*)d_in[10];
    const float* wk    = (const float*)d_in[11];
    const float* wv    = (const float*)d_in[12];
    const float* wqn   = (const float*)d_in[13];
    const float* wkn   = (const float*)d_in[14];
    const float* wo    = (const float*)d_in[15];
    const float* wpost = (const float*)d_in[16];
    const float* wgate = (const float*)d_in[17];
    const float* wup   = (const float*)d_in[18];
    const float* wdown = (const float*)d_in[19];
    const float* wfin  = (const float*)d_in[20];
    const float* wlm   = (const float*)d_in[21];

    float* out  = (float*)d_out;
    float* outk = out + BB * VV;
    float* outv = outk + (size_t)NL * BB * KVH * HDIM * TT;

    static float* sp = nullptr;
    if (!sp) {
        cudaGetSymbolAddress((void**)&sp, g_scratch);
        cudaFuncSetAttribute(k_attn_part, cudaFuncAttributeMaxDynamicSharedMemorySize,
                             73728);
    }
    float* g_h     = sp;
    float* g_hn    = sp + 6144;
    float* g_qkv   = sp + 12288;
    float* g_q     = sp + 19968;
    float* g_attn  = sp + 26112;
    float* g_gu    = sp + 32256;
    float* g_apart = sp + 69120;
    float* g_part  = sp + 268800;

    k_copy_k<<<NL * BB * KVH * HDIM, 256>>>(pastk, outk);
    {
        dim3 g((TPAST * HDIM / 4 + 255) / 256, NL * BB * KVH);
        k_copy_v<<<g, 256>>>((const float4*)pastv, (float4*)outv);
    }

    const float* hptr = hid;
    for (int l = 0; l < NL; ++l) {
        k_rmsnorm<<<BB, 256>>>(hptr, w_in + l * DD, g_hn);
        // QKV: Ntot=2560, 128 splits of 16
        k_gemv_t<16><<<dim3(3, 128), 256>>>(g_hn, nullptr, nullptr, DD,
            wq + (size_t)l * DD * 2048, 2048,
            wk + (size_t)l * DD * 256, 256,
            wv + (size_t)l * DD * 256, 256, 2560, g_part);
        k_reduce<<<30, 256>>>(g_part, 128, 2560, nullptr, nullptr, g_qkv);

        k_rope<<<BB * HH + BB * KVH, 128>>>(g_qkv, wqn + l * HDIM, wkn + l * HDIM,
                                            cosq, sinq, cosk, sink,
                                            g_q, outk, outv, l);

        k_attn_part<<<dim3(NCH, BB * KVH), 256, 73728>>>(g_q, outk, outv, ascl,
                                                         g_apart, l);
        k_attn_fin<<<BB * HH, 128>>>(g_apart, g_attn);

        // wo: N=2048, 128 splits of 16
        k_gemv_t<16><<<dim3(2, 128), 256>>>(g_attn, nullptr, nullptr, DD,
            wo + (size_t)l * DD * DD, DD, nullptr, 0, nullptr, 0, DD, g_part);
        k_reduce<<<24, 256>>>(g_part, 128, DD, hptr, nullptr, g_h);

        k_rmsnorm<<<BB, 256>>>(g_h, wpost + l * DD, g_hn);
        // gate|up: Ntot=12288, 32 splits of 64
        k_gemv_t<64><<<dim3(12, 32), 256>>>(g_hn, nullptr, nullptr, DD,
            wgate + (size_t)l * DD * FF, FF,
            wup + (size_t)l * DD * FF, FF,
            nullptr, 0, 2 * FF, g_part);
        k_reduce<<<144, 256>>>(g_part, 32, 2 * FF, nullptr, nullptr, g_gu);

        // down (fused silu*up): N=2048, 192 splits of 32 over D=6144
        k_gemv_t<32><<<dim3(2, 192), 256>>>(nullptr, g_gu, g_gu + FF, 2 * FF,
            wdown + (size_t)l * FF * DD, DD, nullptr, 0, nullptr, 0, DD, g_part);
        const float* ds = (l < 3) ? (deeps + (size_t)l * BB * DD) : nullptr;
        k_reduce<<<24, 256>>>(g_part, 192, DD, g_h, ds, g_h);
        hptr = g_h;
    }

    k_rmsnorm<<<BB, 256>>>(g_h, wfin, g_hn);
    // lm_head: N=32000, 16 splits of 128
    k_gemv_t<128><<<dim3(32, 16), 256>>>(g_hn, nullptr, nullptr, DD,
        wlm, VV, nullptr, 0, nullptr, 0, VV, g_part);
    k_reduce<<<375, 256>>>(g_part, 16, VV, nullptr, nullptr, out);
}

// round 5
// speedup vs baseline: 2.3755x; 1.1231x over previous
#include <cuda_runtime.h>
#include <cuda_bf16.h>
#include <cstdint>
#include <cstddef>

#define BB 3
#define DD 2048
#define HH 16
#define HDIM 128
#define KVH 2
#define FF 6144
#define VV 32000
#define TT 4096
#define TPAST 4095
#define NL 4
#define GQ (HH / KVH)   // 8
#define NCH 32
#define CT 128
#define CS (GQ * HDIM + 2 * GQ)   // 1040

__device__ float g_scratch[268800 + 1600000];

// ---------------- rmsnorm ----------------
__global__ void k_rmsnorm(const float* __restrict__ x, const float* __restrict__ w,
                          float* __restrict__ y) {
    int b = blockIdx.x;
    const float* xb = x + b * DD;
    __shared__ float red[256];
    float ss = 0.f;
    for (int i = threadIdx.x; i < DD; i += 256) { float v = xb[i]; ss += v * v; }
    red[threadIdx.x] = ss;
    __syncthreads();
    for (int s = 128; s > 0; s >>= 1) {
        if (threadIdx.x < s) red[threadIdx.x] += red[threadIdx.x + s];
        __syncthreads();
    }
    float rs = rsqrtf(red[0] * (1.f / DD) + 1e-6f);
    for (int i = threadIdx.x; i < DD; i += 256) y[b * DD + i] = xb[i] * rs * w[i];
}

// ---------------- split-K GEMV, software-pipelined, NTHR threads ----------------
template <int DC, int NTHR>
__global__ __launch_bounds__(NTHR) void k_gemv_t(
        const float* __restrict__ x,
        const float* __restrict__ xg, const float* __restrict__ xu, int xstride,
        const float* __restrict__ W0, int n0,
        const float* __restrict__ W1, int n1,
        const float* __restrict__ W2, int n2,
        int Ntot, float* __restrict__ part) {
    __shared__ float xs[BB * DC];
    int d0 = blockIdx.y * DC;
    int n = (blockIdx.x * NTHR + threadIdx.x) * 4;
    bool active = n < Ntot;

    const float4* Wr = nullptr;
    size_t ld4 = 0;
    if (active) {
        const float* Wp; int c, ld;
        if (n < n0)            { Wp = W0; c = n;           ld = n0; }
        else if (n < n0 + n1)  { Wp = W1; c = n - n0;      ld = n1; }
        else                   { Wp = W2; c = n - n0 - n1; ld = n2; }
        Wr = reinterpret_cast<const float4*>(Wp + (size_t)d0 * ld) + (c >> 2);
        ld4 = (size_t)(ld >> 2);
    }

    // first weight batch issued before x staging
    float4 w[8];
    if (active) {
#pragma unroll
        for (int u = 0; u < 8; ++u) w[u] = __ldg(Wr + (size_t)u * ld4);
    }

    for (int i = threadIdx.x; i < BB * DC; i += NTHR) {
        int b = i / DC, d = i - b * DC;
        float v;
        if (xg) {
            float g = xg[b * xstride + d0 + d];
            float u = xu[b * xstride + d0 + d];
            v = (g / (1.f + __expf(-g))) * u;
        } else {
            v = x[b * xstride + d0 + d];
        }
        xs[i] = v;
    }
    __syncthreads();

    float4 a0 = {0,0,0,0}, a1 = {0,0,0,0}, a2 = {0,0,0,0};
    if (active) {
#pragma unroll
        for (int d = 0; d < DC; d += 8) {
            float4 w2[8];
            if (d + 8 < DC) {
#pragma unroll
                for (int u = 0; u < 8; ++u)
                    w2[u] = __ldg(Wr + (size_t)(d + 8 + u) * ld4);
            }
#pragma unroll
            for (int u = 0; u < 8; ++u) {
                float x0 = xs[d + u], x1 = xs[DC + d + u], x2 = xs[2 * DC + d + u];
                a0.x += x0 * w[u].x; a0.y += x0 * w[u].y; a0.z += x0 * w[u].z; a0.w += x0 * w[u].w;
                a1.x += x1 * w[u].x; a1.y += x1 * w[u].y; a1.z += x1 * w[u].z; a1.w += x1 * w[u].w;
                a2.x += x2 * w[u].x; a2.y += x2 * w[u].y; a2.z += x2 * w[u].z; a2.w += x2 * w[u].w;
            }
            if (d + 8 < DC) {
#pragma unroll
                for (int u = 0; u < 8; ++u) w[u] = w2[u];
            }
        }
        float* P = part + (size_t)blockIdx.y * BB * Ntot;
        *(float4*)(P + 0 * (size_t)Ntot + n) = a0;
        *(float4*)(P + 1 * (size_t)Ntot + n) = a1;
        *(float4*)(P + 2 * (size_t)Ntot + n) = a2;
    }
}

// ---------------- reduce over splits (+residuals), float4 ----------------
__global__ void k_reduce(const float* __restrict__ part, int S, int Ntot,
                         const float* __restrict__ r1, const float* __restrict__ r2,
                         float* __restrict__ y) {
    int tot4 = BB * Ntot / 4;
    const float4* P4 = (const float4*)part;
    for (int i = blockIdx.x * 256 + threadIdx.x; i < tot4; i += gridDim.x * 256) {
        float4 a = {0,0,0,0};
        if (r1) a = ((const float4*)r1)[i];
        if (r2) { float4 t = ((const float4*)r2)[i]; a.x += t.x; a.y += t.y; a.z += t.z; a.w += t.w; }
        for (int s = 0; s < S; ++s) {
            float4 p = P4[(size_t)s * tot4 + i];
            a.x += p.x; a.y += p.y; a.z += p.z; a.w += p.w;
        }
        ((float4*)y)[i] = a;
    }
}

// ---------------- per-head RMSNorm + RoPE ----------------
__global__ void k_rope(const float* __restrict__ qkv,
                       const float* __restrict__ wqn, const float* __restrict__ wkn,
                       const float* __restrict__ cq, const float* __restrict__ sq,
                       const float* __restrict__ ck, const float* __restrict__ sk,
                       float* __restrict__ qout, float* __restrict__ kcache,
                       float* __restrict__ vcache, int l) {
    __shared__ float nsh[HDIM];
    __shared__ float red[4];
    int t = threadIdx.x;
    int blk = blockIdx.x;
    const float scale = 0.29730177875068026f;  // 128^-0.25
    if (blk < BB * HH) {
        int b = blk / HH, h = blk % HH;
        float v = qkv[b * 2560 + h * HDIM + t];
        float ss = v * v;
        for (int o = 16; o; o >>= 1) ss += __shfl_xor_sync(0xffffffff, ss, o);
        if ((t & 31) == 0) red[t >> 5] = ss;
        __syncthreads();
        float tot = red[0] + red[1] + red[2] + red[3];
        float rs = rsqrtf(tot * (1.f / HDIM) + 1e-6f);
        float nv = v * rs * wqn[t] * scale;
        nsh[t] = nv;
        __syncthreads();
        float partner = (t < 64) ? -nsh[t + 64] : nsh[t - 64];
        qout[b * HH * HDIM + h * HDIM + t] = nv * cq[t] + partner * sq[t];
    } else {
        int j = blk - BB * HH;
        int b = j / KVH, kh = j % KVH;
        float v = qkv[b * 2560 + 2048 + kh * HDIM + t];
        float ss = v * v;
        for (int o = 16; o; o >>= 1) ss += __shfl_xor_sync(0xffffffff, ss, o);
        if ((t & 31) == 0) red[t >> 5] = ss;
        __syncthreads();
        float tot = red[0] + red[1] + red[2] + red[3];
        float rs = rsqrtf(tot * (1.f / HDIM) + 1e-6f);
        float nv = v * rs * wkn[t] * scale;
        nsh[t] = nv;
        __syncthreads();
        float partner = (t < 64) ? -nsh[t + 64] : nsh[t - 64];
        float kval = nv * ck[t] + partner * sk[t];
        size_t kb = ((size_t)(l * BB + b) * KVH + kh) * (size_t)HDIM * TT;
        kcache[kb + (size_t)t * TT + TPAST] = kval;
        size_t vb = ((size_t)(l * BB + b) * KVH + kh) * (size_t)TT * HDIM;
        vcache[vb + (size_t)TPAST * HDIM + t] = qkv[b * 2560 + 2304 + kh * HDIM + t];
    }
}

// ---------------- flash-decode attention partial ----------------
__global__ __launch_bounds__(256) void k_attn_part(
        const float* __restrict__ q, const float* __restrict__ kc,
        const float* __restrict__ vc, const float* __restrict__ ascale_p,
        float* __restrict__ po, int l) {
    extern __shared__ float smem[];
    float* tile = smem;
    float* qs   = smem + 16384;
    float* ps   = smem + 17408;
    int tid = threadIdx.x;
    int c = blockIdx.x;
    int by = blockIdx.y;
    int b = by / KVH, kh = by % KVH;
    int t0 = c * CT;
    float madd = -128.f * ascale_p[0];

    {
        float4 v = *(const float4*)(q + b * HH * HDIM + kh * GQ * HDIM + tid * 4);
        *(float4*)(qs + tid * 4) = v;
    }
    {
        const float* Kb = kc + (((size_t)(l * BB + b) * KVH + kh) * HDIM) * TT + t0;
        const float4* Ks = (const float4*)Kb;
        float4* Td = (float4*)tile;
        for (int i = tid; i < HDIM * CT / 4; i += 256) {
            int row = i >> 5, col = i & 31;
            Td[i] = __ldg(Ks + (size_t)row * (TT / 4) + col);
        }
    }
    __syncthreads();

    {
        int t = tid & 127, hb = tid >> 7;
        float a[4] = {0.f, 0.f, 0.f, 0.f};
        for (int d = 0; d < HDIM; ++d) {
            float kv = tile[d * CT + t];
#pragma unroll
            for (int g2 = 0; g2 < 4; ++g2)
                a[g2] += kv * qs[(hb * 4 + g2) * HDIM + d];
        }
        float mk = (t0 + t > 0) ? madd : 0.f;
#pragma unroll
        for (int g2 = 0; g2 < 4; ++g2)
            ps[(hb * 4 + g2) * CT + t] = a[g2] + mk;
    }
    __syncthreads();

    {
        int w = tid >> 5, lane = tid & 31;
        float mx = -1e30f;
        for (int j = lane; j < CT; j += 32) mx = fmaxf(mx, ps[w * CT + j]);
        for (int o = 16; o; o >>= 1) mx = fmaxf(mx, __shfl_xor_sync(0xffffffff, mx, o));
        float sum = 0.f;
        for (int j = lane; j < CT; j += 32) {
            float e = __expf(ps[w * CT + j] - mx);
            ps[w * CT + j] = e;
            sum += e;
        }
        for (int o = 16; o; o >>= 1) sum += __shfl_xor_sync(0xffffffff, sum, o);
        if (lane == 0) {
            float* rec = po + ((size_t)by * NCH + c) * CS;
            rec[GQ * HDIM + w] = mx;
            rec[GQ * HDIM + GQ + w] = sum;
        }
    }
    __syncthreads();

    {
        const float4* Vs = (const float4*)(vc +
            ((size_t)(l * BB + b) * KVH + kh) * (size_t)TT * HDIM + (size_t)t0 * HDIM);
        float4* Td = (float4*)tile;
        for (int i = tid; i < CT * HDIM / 4; i += 256) Td[i] = __ldg(Vs + i);
    }
    __syncthreads();

    {
        int d = tid & 127, hb = tid >> 7;
        float o[4] = {0.f, 0.f, 0.f, 0.f};
        for (int t = 0; t < CT; ++t) {
            float vv = tile[t * HDIM + d];
#pragma unroll
            for (int g2 = 0; g2 < 4; ++g2)
                o[g2] += vv * ps[(hb * 4 + g2) * CT + t];
        }
        float* rec = po + ((size_t)by * NCH + c) * CS;
#pragma unroll
        for (int g2 = 0; g2 < 4; ++g2)
            rec[(hb * 4 + g2) * HDIM + d] = o[g2];
    }
}

// ---------------- combine attention chunks ----------------
__global__ void k_attn_fin(const float* __restrict__ po, float* __restrict__ out) {
    int b = blockIdx.x / HH, h = blockIdx.x % HH;
    int kh = h >> 3, g = h & 7;
    int tid = threadIdx.x;
    const float* base = po + (size_t)(b * KVH + kh) * NCH * CS;
    float m = -1e30f;
    for (int c = 0; c < NCH; ++c) m = fmaxf(m, base[c * CS + GQ * HDIM + g]);
    float den = 0.f, acc = 0.f;
    for (int c = 0; c < NCH; ++c) {
        float mc = base[c * CS + GQ * HDIM + g];
        float lc = base[c * CS + GQ * HDIM + GQ + g];
        float w = __expf(mc - m);
        den += lc * w;
        acc += base[c * CS + g * HDIM + tid] * w;
    }
    out[b * HH * HDIM + h * HDIM + tid] = acc / den;
}

// ---------------- past-cache copies ----------------
__global__ void k_copy_k(const float* __restrict__ pk, float* __restrict__ outk) {
    int r = blockIdx.x;
    const float* src = pk + (size_t)r * TPAST;
    float* dst = outk + (size_t)r * TT;
    int t = threadIdx.x;
#pragma unroll 4
    for (int i = 0; i < 16; ++i) {
        int idx = i * 256 + t;
        if (idx < TPAST) dst[idx] = __ldg(src + idx);
    }
}
__global__ void k_copy_v(const float4* __restrict__ pv, float4* __restrict__ outv) {
    const int per = TPAST * HDIM / 4;
    int ch = blockIdx.y;
    int i = blockIdx.x * 256 + threadIdx.x;
    if (i < per)
        outv[(size_t)ch * (TT * HDIM / 4) + i] = __ldg(pv + (size_t)ch * per + i);
}

// ---------------- host ----------------
extern "C" void kernel_launch(void* const* d_in, const int* in_sizes, int n_in,
                              void* d_out, int out_size) {
    const float* hid   = (const float*)d_in[0];
    const float* pastk = (const float*)d_in[1];
    const float* pastv = (const float*)d_in[2];
    const float* deeps = (const float*)d_in[3];
    const float* cosq  = (const float*)d_in[4];
    const float* sinq  = (const float*)d_in[5];
    const float* cosk  = (const float*)d_in[6];
    const float* sink  = (const float*)d_in[7];
    const float* ascl  = (const float*)d_in[8];
    const float* w_in  = (const float*)d_in[9];
    const float* wq    = (const float*)d_in[10];
    const float* wk    = (const float*)d_in[11];
    const float* wv    = (const float*)d_in[12];
    const float* wqn   = (const float*)d_in[13];
    const float* wkn   = (const float*)d_in[14];
    const float* wo    = (const float*)d_in[15];
    const float* wpost = (const float*)d_in[16];
    const float* wgate = (const float*)d_in[17];
    const float* wup   = (const float*)d_in[18];
    const float* wdown = (const float*)d_in[19];
    const float* wfin  = (const float*)d_in[20];
    const float* wlm   = (const float*)d_in[21];

    float* out  = (float*)d_out;
    float* outk = out + BB * VV;
    float* outv = outk + (size_t)NL * BB * KVH * HDIM * TT;

    static float* sp = nullptr;
    if (!sp) {
        cudaGetSymbolAddress((void**)&sp, g_scratch);
        cudaFuncSetAttribute(k_attn_part, cudaFuncAttributeMaxDynamicSharedMemorySize,
                             73728);
    }
    float* g_h     = sp;
    float* g_hn    = sp + 6144;
    float* g_qkv   = sp + 12288;
    float* g_q     = sp + 19968;
    float* g_attn  = sp + 26112;
    float* g_gu    = sp + 32256;
    float* g_apart = sp + 69120;
    float* g_part  = sp + 268800;

    k_copy_k<<<NL * BB * KVH * HDIM, 256>>>(pastk, outk);
    {
        dim3 g((TPAST * HDIM / 4 + 255) / 256, NL * BB * KVH);
        k_copy_v<<<g, 256>>>((const float4*)pastv, (float4*)outv);
    }

    const float* hptr = hid;
    for (int l = 0; l < NL; ++l) {
        k_rmsnorm<<<BB, 256>>>(hptr, w_in + l * DD, g_hn);
        // QKV: Ntot=2560 -> 640 f4 cols = 5 blocks x 128 thr (exact); 64 splits of 32
        k_gemv_t<32, 128><<<dim3(5, 64), 128>>>(g_hn, nullptr, nullptr, DD,
            wq + (size_t)l * DD * 2048, 2048,
            wk + (size_t)l * DD * 256, 256,
            wv + (size_t)l * DD * 256, 256, 2560, g_part);
        k_reduce<<<30, 256>>>(g_part, 64, 2560, nullptr, nullptr, g_qkv);

        k_rope<<<BB * HH + BB * KVH, 128>>>(g_qkv, wqn + l * HDIM, wkn + l * HDIM,
                                            cosq, sinq, cosk, sink,
                                            g_q, outk, outv, l);

        k_attn_part<<<dim3(NCH, BB * KVH), 256, 73728>>>(g_q, outk, outv, ascl,
                                                         g_apart, l);
        k_attn_fin<<<BB * HH, 128>>>(g_apart, g_attn);

        // wo: N=2048 -> 512 f4 = 4 blocks x 128 (exact); 64 splits of 32
        k_gemv_t<32, 128><<<dim3(4, 64), 128>>>(g_attn, nullptr, nullptr, DD,
            wo + (size_t)l * DD * DD, DD, nullptr, 0, nullptr, 0, DD, g_part);
        k_reduce<<<24, 256>>>(g_part, 64, DD, hptr, nullptr, g_h);

        k_rmsnorm<<<BB, 256>>>(g_h, wpost + l * DD, g_hn);
        // gate|up: Ntot=12288 -> 3072 f4 = 24 blocks x 128 (exact); 32 splits of 64
        k_gemv_t<64, 128><<<dim3(24, 32), 128>>>(g_hn, nullptr, nullptr, DD,
            wgate + (size_t)l * DD * FF, FF,
            wup + (size_t)l * DD * FF, FF,
            nullptr, 0, 2 * FF, g_part);
        k_reduce<<<144, 256>>>(g_part, 32, 2 * FF, nullptr, nullptr, g_gu);

        // down (fused silu*up): N=2048 -> 4 blocks x 128 (exact); 96 splits of 64
        k_gemv_t<64, 128><<<dim3(4, 96), 128>>>(nullptr, g_gu, g_gu + FF, 2 * FF,
            wdown + (size_t)l * FF * DD, DD, nullptr, 0, nullptr, 0, DD, g_part);
        const float* ds = (l < 3) ? (deeps + (size_t)l * BB * DD) : nullptr;
        k_reduce<<<24, 256>>>(g_part, 96, DD, g_h, ds, g_h);
        hptr = g_h;
    }

    k_rmsnorm<<<BB, 256>>>(g_h, wfin, g_hn);
    // lm_head: N=32000 -> 8000 f4 -> 63 blocks x 128; 16 splits of 128
    k_gemv_t<128, 128><<<dim3(63, 16), 128>>>(g_hn, nullptr, nullptr, DD,
        wlm, VV, nullptr, 0, nullptr, 0, VV, g_part);
    k_reduce<<<375, 256>>>(g_part, 16, VV, nullptr, nullptr, out);
}

// round 6
// speedup vs baseline: 2.6391x; 1.1110x over previous
#include <cuda_runtime.h>
#include <cuda_bf16.h>
#include <cstdint>
#include <cstddef>

#define BB 3
#define DD 2048
#define HH 16
#define HDIM 128
#define KVH 2
#define FF 6144
#define VV 32000
#define TT 4096
#define TPAST 4095
#define NL 4
#define GQ (HH / KVH)   // 8
#define NCH 32
#define CT 128
#define CS (GQ * HDIM + 2 * GQ)   // 1040

__device__ float g_scratch[268800 + 1600000];

__device__ __forceinline__ uint32_t smem_u32(const void* p) {
    return (uint32_t)__cvta_generic_to_shared(p);
}

// ---------------- rmsnorm ----------------
__global__ void k_rmsnorm(const float* __restrict__ x, const float* __restrict__ w,
                          float* __restrict__ y) {
    int b = blockIdx.x;
    const float* xb = x + b * DD;
    __shared__ float red[256];
    float ss = 0.f;
    for (int i = threadIdx.x; i < DD; i += 256) { float v = xb[i]; ss += v * v; }
    red[threadIdx.x] = ss;
    __syncthreads();
    for (int s = 128; s > 0; s >>= 1) {
        if (threadIdx.x < s) red[threadIdx.x] += red[threadIdx.x + s];
        __syncthreads();
    }
    float rs = rsqrtf(red[0] * (1.f / DD) + 1e-6f);
    for (int i = threadIdx.x; i < DD; i += 256) y[b * DD + i] = xb[i] * rs * w[i];
}

// ---------------- split-K GEMV with cp.async 4-stage smem pipeline ----------------
// block: 128 threads, each owns one float4 column. Stage = SR(8) rows x 128 f4.
// Each thread reads back only the smem words it wrote -> no __syncthreads in loop.
template <int DC>
__global__ __launch_bounds__(128) void k_gemv_cp(
        const float* __restrict__ x,
        const float* __restrict__ xg, const float* __restrict__ xu, int xstride,
        const float* __restrict__ W0, int n0,
        const float* __restrict__ W1, int n1,
        const float* __restrict__ W2, int n2,
        int Ntot, float* __restrict__ part) {
    constexpr int SR = 8;
    constexpr int NS = 4;
    constexpr int STAGES = DC / SR;
    extern __shared__ float4 sm4[];
    float4* wt = sm4;                               // [NS][SR][128]
    float* xs = (float*)(sm4 + NS * SR * 128);      // [BB][DC]

    int tid = threadIdx.x;
    int d0 = blockIdx.y * DC;
    int c4 = blockIdx.x * 128 + tid;
    int n = c4 * 4;
    bool active = n < Ntot;

    const float4* Wr = nullptr;
    size_t ld4 = 0;
    if (active) {
        const float* Wp; int c, ld;
        if (n < n0)            { Wp = W0; c = n;           ld = n0; }
        else if (n < n0 + n1)  { Wp = W1; c = n - n0;      ld = n1; }
        else                   { Wp = W2; c = n - n0 - n1; ld = n2; }
        Wr = reinterpret_cast<const float4*>(Wp + (size_t)d0 * ld) + (c >> 2);
        ld4 = (size_t)(ld >> 2);
    }

    // prologue: issue NS-1 stages
#pragma unroll
    for (int s = 0; s < NS - 1; ++s) {
        if (active) {
            float4* dst = wt + (s * SR) * 128 + tid;
            const float4* src = Wr + (size_t)(s * SR) * ld4;
#pragma unroll
            for (int r = 0; r < SR; ++r)
                asm volatile("cp.async.cg.shared.global [%0], [%1], 16;\n"
                             :: "r"(smem_u32(dst + r * 128)), "l"(src + r * ld4));
        }
        asm volatile("cp.async.commit_group;\n");
    }

    // stage x (overlapped with async weight prologue)
    for (int i = tid; i < BB * DC; i += 128) {
        int b = i / DC, d = i - b * DC;
        float v;
        if (xg) {
            float g = xg[b * xstride + d0 + d];
            float u = xu[b * xstride + d0 + d];
            v = (g / (1.f + __expf(-g))) * u;
        } else {
            v = x[b * xstride + d0 + d];
        }
        xs[i] = v;
    }
    __syncthreads();

    float4 a0 = {0,0,0,0}, a1 = {0,0,0,0}, a2 = {0,0,0,0};
    for (int s = 0; s < STAGES; ++s) {
        int sn = s + NS - 1;
        if (sn < STAGES && active) {
            float4* dst = wt + ((sn % NS) * SR) * 128 + tid;
            const float4* src = Wr + (size_t)(sn * SR) * ld4;
#pragma unroll
            for (int r = 0; r < SR; ++r)
                asm volatile("cp.async.cg.shared.global [%0], [%1], 16;\n"
                             :: "r"(smem_u32(dst + r * 128)), "l"(src + r * ld4));
        }
        asm volatile("cp.async.commit_group;\n");
        asm volatile("cp.async.wait_group 3;\n");   // stage s complete (own data)
        int buf = s % NS;
        if (active) {
#pragma unroll
            for (int r = 0; r < SR; ++r) {
                float4 w = wt[(buf * SR + r) * 128 + tid];
                int d = s * SR + r;
                float x0 = xs[d], x1 = xs[DC + d], x2 = xs[2 * DC + d];
                a0.x += x0 * w.x; a0.y += x0 * w.y; a0.z += x0 * w.z; a0.w += x0 * w.w;
                a1.x += x1 * w.x; a1.y += x1 * w.y; a1.z += x1 * w.z; a1.w += x1 * w.w;
                a2.x += x2 * w.x; a2.y += x2 * w.y; a2.z += x2 * w.z; a2.w += x2 * w.w;
            }
        }
    }
    if (active) {
        float* P = part + (size_t)blockIdx.y * BB * Ntot;
        *(float4*)(P + 0 * (size_t)Ntot + n) = a0;
        *(float4*)(P + 1 * (size_t)Ntot + n) = a1;
        *(float4*)(P + 2 * (size_t)Ntot + n) = a2;
    }
}

// ---------------- reduce over splits (+residuals), float4 ----------------
__global__ void k_reduce(const float* __restrict__ part, int S, int Ntot,
                         const float* __restrict__ r1, const float* __restrict__ r2,
                         float* __restrict__ y) {
    int tot4 = BB * Ntot / 4;
    const float4* P4 = (const float4*)part;
    for (int i = blockIdx.x * 256 + threadIdx.x; i < tot4; i += gridDim.x * 256) {
        float4 a = {0,0,0,0};
        if (r1) a = ((const float4*)r1)[i];
        if (r2) { float4 t = ((const float4*)r2)[i]; a.x += t.x; a.y += t.y; a.z += t.z; a.w += t.w; }
        for (int s = 0; s < S; ++s) {
            float4 p = P4[(size_t)s * tot4 + i];
            a.x += p.x; a.y += p.y; a.z += p.z; a.w += p.w;
        }
        ((float4*)y)[i] = a;
    }
}

// ---------------- per-head RMSNorm + RoPE ----------------
__global__ void k_rope(const float* __restrict__ qkv,
                       const float* __restrict__ wqn, const float* __restrict__ wkn,
                       const float* __restrict__ cq, const float* __restrict__ sq,
                       const float* __restrict__ ck, const float* __restrict__ sk,
                       float* __restrict__ qout, float* __restrict__ kcache,
                       float* __restrict__ vcache, int l) {
    __shared__ float nsh[HDIM];
    __shared__ float red[4];
    int t = threadIdx.x;
    int blk = blockIdx.x;
    const float scale = 0.29730177875068026f;  // 128^-0.25
    if (blk < BB * HH) {
        int b = blk / HH, h = blk % HH;
        float v = qkv[b * 2560 + h * HDIM + t];
        float ss = v * v;
        for (int o = 16; o; o >>= 1) ss += __shfl_xor_sync(0xffffffff, ss, o);
        if ((t & 31) == 0) red[t >> 5] = ss;
        __syncthreads();
        float tot = red[0] + red[1] + red[2] + red[3];
        float rs = rsqrtf(tot * (1.f / HDIM) + 1e-6f);
        float nv = v * rs * wqn[t] * scale;
        nsh[t] = nv;
        __syncthreads();
        float partner = (t < 64) ? -nsh[t + 64] : nsh[t - 64];
        qout[b * HH * HDIM + h * HDIM + t] = nv * cq[t] + partner * sq[t];
    } else {
        int j = blk - BB * HH;
        int b = j / KVH, kh = j % KVH;
        float v = qkv[b * 2560 + 2048 + kh * HDIM + t];
        float ss = v * v;
        for (int o = 16; o; o >>= 1) ss += __shfl_xor_sync(0xffffffff, ss, o);
        if ((t & 31) == 0) red[t >> 5] = ss;
        __syncthreads();
        float tot = red[0] + red[1] + red[2] + red[3];
        float rs = rsqrtf(tot * (1.f / HDIM) + 1e-6f);
        float nv = v * rs * wkn[t] * scale;
        nsh[t] = nv;
        __syncthreads();
        float partner = (t < 64) ? -nsh[t + 64] : nsh[t - 64];
        float kval = nv * ck[t] + partner * sk[t];
        size_t kb = ((size_t)(l * BB + b) * KVH + kh) * (size_t)HDIM * TT;
        kcache[kb + (size_t)t * TT + TPAST] = kval;
        size_t vb = ((size_t)(l * BB + b) * KVH + kh) * (size_t)TT * HDIM;
        vcache[vb + (size_t)TPAST * HDIM + t] = qkv[b * 2560 + 2304 + kh * HDIM + t];
    }
}

// ---------------- flash-decode attention partial ----------------
__global__ __launch_bounds__(256) void k_attn_part(
        const float* __restrict__ q, const float* __restrict__ kc,
        const float* __restrict__ vc, const float* __restrict__ ascale_p,
        float* __restrict__ po, int l) {
    extern __shared__ float smem[];
    float* tile = smem;
    float* qs   = smem + 16384;
    float* ps   = smem + 17408;
    int tid = threadIdx.x;
    int c = blockIdx.x;
    int by = blockIdx.y;
    int b = by / KVH, kh = by % KVH;
    int t0 = c * CT;
    float madd = -128.f * ascale_p[0];

    {
        float4 v = *(const float4*)(q + b * HH * HDIM + kh * GQ * HDIM + tid * 4);
        *(float4*)(qs + tid * 4) = v;
    }
    {
        const float* Kb = kc + (((size_t)(l * BB + b) * KVH + kh) * HDIM) * TT + t0;
        const float4* Ks = (const float4*)Kb;
        float4* Td = (float4*)tile;
        for (int i = tid; i < HDIM * CT / 4; i += 256) {
            int row = i >> 5, col = i & 31;
            Td[i] = __ldg(Ks + (size_t)row * (TT / 4) + col);
        }
    }
    __syncthreads();

    {
        int t = tid & 127, hb = tid >> 7;
        float a[4] = {0.f, 0.f, 0.f, 0.f};
        for (int d = 0; d < HDIM; ++d) {
            float kv = tile[d * CT + t];
#pragma unroll
            for (int g2 = 0; g2 < 4; ++g2)
                a[g2] += kv * qs[(hb * 4 + g2) * HDIM + d];
        }
        float mk = (t0 + t > 0) ? madd : 0.f;
#pragma unroll
        for (int g2 = 0; g2 < 4; ++g2)
            ps[(hb * 4 + g2) * CT + t] = a[g2] + mk;
    }
    __syncthreads();

    {
        int w = tid >> 5, lane = tid & 31;
        float mx = -1e30f;
        for (int j = lane; j < CT; j += 32) mx = fmaxf(mx, ps[w * CT + j]);
        for (int o = 16; o; o >>= 1) mx = fmaxf(mx, __shfl_xor_sync(0xffffffff, mx, o));
        float sum = 0.f;
        for (int j = lane; j < CT; j += 32) {
            float e = __expf(ps[w * CT + j] - mx);
            ps[w * CT + j] = e;
            sum += e;
        }
        for (int o = 16; o; o >>= 1) sum += __shfl_xor_sync(0xffffffff, sum, o);
        if (lane == 0) {
            float* rec = po + ((size_t)by * NCH + c) * CS;
            rec[GQ * HDIM + w] = mx;
            rec[GQ * HDIM + GQ + w] = sum;
        }
    }
    __syncthreads();

    {
        const float4* Vs = (const float4*)(vc +
            ((size_t)(l * BB + b) * KVH + kh) * (size_t)TT * HDIM + (size_t)t0 * HDIM);
        float4* Td = (float4*)tile;
        for (int i = tid; i < CT * HDIM / 4; i += 256) Td[i] = __ldg(Vs + i);
    }
    __syncthreads();

    {
        int d = tid & 127, hb = tid >> 7;
        float o[4] = {0.f, 0.f, 0.f, 0.f};
        for (int t = 0; t < CT; ++t) {
            float vv = tile[t * HDIM + d];
#pragma unroll
            for (int g2 = 0; g2 < 4; ++g2)
                o[g2] += vv * ps[(hb * 4 + g2) * CT + t];
        }
        float* rec = po + ((size_t)by * NCH + c) * CS;
#pragma unroll
        for (int g2 = 0; g2 < 4; ++g2)
            rec[(hb * 4 + g2) * HDIM + d] = o[g2];
    }
}

// ---------------- combine attention chunks ----------------
__global__ void k_attn_fin(const float* __restrict__ po, float* __restrict__ out) {
    int b = blockIdx.x / HH, h = blockIdx.x % HH;
    int kh = h >> 3, g = h & 7;
    int tid = threadIdx.x;
    const float* base = po + (size_t)(b * KVH + kh) * NCH * CS;
    float m = -1e30f;
    for (int c = 0; c < NCH; ++c) m = fmaxf(m, base[c * CS + GQ * HDIM + g]);
    float den = 0.f, acc = 0.f;
    for (int c = 0; c < NCH; ++c) {
        float mc = base[c * CS + GQ * HDIM + g];
        float lc = base[c * CS + GQ * HDIM + GQ + g];
        float w = __expf(mc - m);
        den += lc * w;
        acc += base[c * CS + g * HDIM + tid] * w;
    }
    out[b * HH * HDIM + h * HDIM + tid] = acc / den;
}

// ---------------- past-cache copies ----------------
__global__ void k_copy_k(const float* __restrict__ pk, float* __restrict__ outk) {
    int r = blockIdx.x;
    const float* src = pk + (size_t)r * TPAST;
    float* dst = outk + (size_t)r * TT;
    int t = threadIdx.x;
#pragma unroll 4
    for (int i = 0; i < 16; ++i) {
        int idx = i * 256 + t;
        if (idx < TPAST) dst[idx] = __ldg(src + idx);
    }
}
__global__ void k_copy_v(const float4* __restrict__ pv, float4* __restrict__ outv) {
    const int per = TPAST * HDIM / 4;
    int ch = blockIdx.y;
    int i = blockIdx.x * 256 + threadIdx.x;
    if (i < per)
        outv[(size_t)ch * (TT * HDIM / 4) + i] = __ldg(pv + (size_t)ch * per + i);
}

// ---------------- host ----------------
extern "C" void kernel_launch(void* const* d_in, const int* in_sizes, int n_in,
                              void* d_out, int out_size) {
    const float* hid   = (const float*)d_in[0];
    const float* pastk = (const float*)d_in[1];
    const float* pastv = (const float*)d_in[2];
    const float* deeps = (const float*)d_in[3];
    const float* cosq  = (const float*)d_in[4];
    const float* sinq  = (const float*)d_in[5];
    const float* cosk  = (const float*)d_in[6];
    const float* sink  = (const float*)d_in[7];
    const float* ascl  = (const float*)d_in[8];
    const float* w_in  = (const float*)d_in[9];
    const float* wq    = (const float*)d_in[10];
    const float* wk    = (const float*)d_in[11];
    const float* wv    = (const float*)d_in[12];
    const float* wqn   = (const float*)d_in[13];
    const float* wkn   = (const float*)d_in[14];
    const float* wo    = (const float*)d_in[15];
    const float* wpost = (const float*)d_in[16];
    const float* wgate = (const float*)d_in[17];
    const float* wup   = (const float*)d_in[18];
    const float* wdown = (const float*)d_in[19];
    const float* wfin  = (const float*)d_in[20];
    const float* wlm   = (const float*)d_in[21];

    float* out  = (float*)d_out;
    float* outk = out + BB * VV;
    float* outv = outk + (size_t)NL * BB * KVH * HDIM * TT;

    static float* sp = nullptr;
    if (!sp) {
        cudaGetSymbolAddress((void**)&sp, g_scratch);
        cudaFuncSetAttribute(k_attn_part, cudaFuncAttributeMaxDynamicSharedMemorySize,
                             73728);
        cudaFuncSetAttribute(k_gemv_cp<64>,  cudaFuncAttributeMaxDynamicSharedMemorySize, 65536 + BB*64*4);
        cudaFuncSetAttribute(k_gemv_cp<128>, cudaFuncAttributeMaxDynamicSharedMemorySize, 65536 + BB*128*4);
        cudaFuncSetAttribute(k_gemv_cp<192>, cudaFuncAttributeMaxDynamicSharedMemorySize, 65536 + BB*192*4);
        cudaFuncSetAttribute(k_gemv_cp<512>, cudaFuncAttributeMaxDynamicSharedMemorySize, 65536 + BB*512*4);
    }
    float* g_h     = sp;
    float* g_hn    = sp + 6144;
    float* g_qkv   = sp + 12288;
    float* g_q     = sp + 19968;
    float* g_attn  = sp + 26112;
    float* g_gu    = sp + 32256;
    float* g_apart = sp + 69120;
    float* g_part  = sp + 268800;

    k_copy_k<<<NL * BB * KVH * HDIM, 256>>>(pastk, outk);
    {
        dim3 g((TPAST * HDIM / 4 + 255) / 256, NL * BB * KVH);
        k_copy_v<<<g, 256>>>((const float4*)pastv, (float4*)outv);
    }

    const float* hptr = hid;
    for (int l = 0; l < NL; ++l) {
        k_rmsnorm<<<BB, 256>>>(hptr, w_in + l * DD, g_hn);
        // QKV: 640 f4 cols -> 5 tiles; 32 splits of 64
        k_gemv_cp<64><<<dim3(5, 32), 128, 65536 + BB*64*4>>>(g_hn, nullptr, nullptr, DD,
            wq + (size_t)l * DD * 2048, 2048,
            wk + (size_t)l * DD * 256, 256,
            wv + (size_t)l * DD * 256, 256, 2560, g_part);
        k_reduce<<<30, 256>>>(g_part, 32, 2560, nullptr, nullptr, g_qkv);

        k_rope<<<BB * HH + BB * KVH, 128>>>(g_qkv, wqn + l * HDIM, wkn + l * HDIM,
                                            cosq, sinq, cosk, sink,
                                            g_q, outk, outv, l);

        k_attn_part<<<dim3(NCH, BB * KVH), 256, 73728>>>(g_q, outk, outv, ascl,
                                                         g_apart, l);
        k_attn_fin<<<BB * HH, 128>>>(g_apart, g_attn);

        // wo: 512 f4 -> 4 tiles; 32 splits of 64
        k_gemv_cp<64><<<dim3(4, 32), 128, 65536 + BB*64*4>>>(g_attn, nullptr, nullptr, DD,
            wo + (size_t)l * DD * DD, DD, nullptr, 0, nullptr, 0, DD, g_part);
        k_reduce<<<24, 256>>>(g_part, 32, DD, hptr, nullptr, g_h);

        k_rmsnorm<<<BB, 256>>>(g_h, wpost + l * DD, g_hn);
        // gate|up: 3072 f4 -> 24 tiles; 16 splits of 128
        k_gemv_cp<128><<<dim3(24, 16), 128, 65536 + BB*128*4>>>(g_hn, nullptr, nullptr, DD,
            wgate + (size_t)l * DD * FF, FF,
            wup + (size_t)l * DD * FF, FF,
            nullptr, 0, 2 * FF, g_part);
        k_reduce<<<144, 256>>>(g_part, 16, 2 * FF, nullptr, nullptr, g_gu);

        // down (fused silu*up): 512 f4 -> 4 tiles; 32 splits of 192 over D=6144
        k_gemv_cp<192><<<dim3(4, 32), 128, 65536 + BB*192*4>>>(nullptr, g_gu, g_gu + FF, 2 * FF,
            wdown + (size_t)l * FF * DD, DD, nullptr, 0, nullptr, 0, DD, g_part);
        const float* ds = (l < 3) ? (deeps + (size_t)l * BB * DD) : nullptr;
        k_reduce<<<24, 256>>>(g_part, 32, DD, g_h, ds, g_h);
        hptr = g_h;
    }

    k_rmsnorm<<<BB, 256>>>(g_h, wfin, g_hn);
    // lm_head: 8000 f4 -> 63 tiles (tail predicated); 4 splits of 512
    k_gemv_cp<512><<<dim3(63, 4), 128, 65536 + BB*512*4>>>(g_hn, nullptr, nullptr, DD,
        wlm, VV, nullptr, 0, nullptr, 0, VV, g_part);
    k_reduce<<<375, 256>>>(g_part, 4, VV, nullptr, nullptr, out);
}